// round 10
// baseline (speedup 1.0000x reference)
#include <cuda_runtime.h>
#include <cuda_fp16.h>
#include <math.h>

// Problem constants
#define BB     64
#define TT     2048
#define DD     40
#define HH     164
#define H_PAD  168             // padded hidden (42 CTAs x 4 cols); pad rows stay exactly 0
#define NOUT   7
#define JT     4
#define NCOL   42              // CTAs per layer
#define NLAYER 3
#define NCTA   (NCOL * NLAYER) // 126
#define CL     3               // cluster size (same-layer triples)
#define TB     256             // 8 warps
#define KMAX   (H_PAD + H_PAD) // 336
#define NCHUNK 4
#define RS     4               // h ring depth -> consumer lag 3
#define NSLOT  8               // counter slots per layer

// ---- dynamic smem layout (bytes) ----
#define OFF_W   0
#define SZ_W    (KMAX * 16 * 8)            // splatted fp32 weights: 43008
#define OFF_X   (OFF_W + SZ_W)
#define SZ_X    (KMAX * BB * 2)            // staged [h;x] fp16: 43008
#define OFF_P   (OFF_X + SZ_X)
#define SZ_P    (NCHUNK * 16 * BB * 4)     // k-split partials: 16384
#define OFF_C   (OFF_P + SZ_P)
#define SZ_C    (JT * BB * 4)
#define OFF_B   (OFF_C + SZ_C)
#define SZ_B    (16 * 4)
#define OFF_L   (OFF_B + SZ_B)
#define SZ_L    (BB * 4)
#define OFF_M   (OFF_L + SZ_L)
#define SZ_M    (NCHUNK * 8)
#define SMEM_BYTES (OFF_M + SZ_M)          // ~104 KB

// ---------------- device scratch ----------------
__device__ __align__(256) __half g_xTh[TT * DD * BB];            // x fp16: [t][d][b]
__device__ __align__(256) __half g_h[NLAYER * RS * H_PAD * BB];  // h ring fp16
__device__ unsigned g_flag[NCTA * 32];                           // Phase-A barrier flags only
__device__ __align__(128) unsigned g_cnt[NLAYER * NSLOT * 32];   // arrival counters, 128B apart

// ---------------- helpers ----------------
__device__ __forceinline__ unsigned long long fma2(unsigned long long a,
                                                   unsigned long long b,
                                                   unsigned long long c) {
    unsigned long long d;
    asm("fma.rn.f32x2 %0, %1, %2, %3;" : "=l"(d) : "l"(a), "l"(b), "l"(c));
    return d;
}
__device__ __forceinline__ unsigned long long splat2(float w) {
    unsigned long long v = (unsigned long long)__float_as_uint(w);
    return v | (v << 32);
}
__device__ __forceinline__ unsigned long long pack2(float lo, float hi) {
    unsigned long long r;
    asm("mov.b64 %0, {%1, %2};" : "=l"(r) : "f"(lo), "f"(hi));
    return r;
}
__device__ __forceinline__ void mc_g2s(void* dst_smem, const void* src, int bytes,
                                       unsigned mbar, unsigned short mask) {
    unsigned d = (unsigned)__cvta_generic_to_shared(dst_smem);
    asm volatile(
        "cp.async.bulk.shared::cluster.global.mbarrier::complete_tx::bytes.multicast::cluster"
        " [%0], [%1], %2, [%3], %4;"
        :: "r"(d), "l"(src), "r"(bytes), "r"(mbar), "h"(mask) : "memory");
}
__device__ __forceinline__ void mbar_init(unsigned addr, unsigned cnt) {
    asm volatile("mbarrier.init.shared.b64 [%0], %1;" :: "r"(addr), "r"(cnt) : "memory");
}
__device__ __forceinline__ void mbar_expect_tx(unsigned addr, unsigned bytes) {
    asm volatile("mbarrier.arrive.expect_tx.shared.b64 _, [%0], %1;" :: "r"(addr), "r"(bytes) : "memory");
}
__device__ __forceinline__ void mbar_wait(unsigned addr, unsigned parity) {
    asm volatile(
        "{\n\t"
        ".reg .pred P1;\n\t"
        "WAIT_%=:\n\t"
        "mbarrier.try_wait.parity.acquire.cta.shared::cta.b64 P1, [%0], %1, 0x989680;\n\t"
        "@P1 bra DONE_%=;\n\t"
        "bra WAIT_%=;\n\t"
        "DONE_%=:\n\t"
        "}"
        :: "r"(addr), "r"(parity) : "memory");
}
__device__ __forceinline__ unsigned flag_acq(const unsigned* p) {
    unsigned r;
    asm volatile("ld.global.acquire.gpu.u32 %0, [%1];" : "=r"(r) : "l"(p));
    return r;
}
__device__ __forceinline__ void flag_rel(unsigned* p, unsigned v) {
    asm volatile("st.global.release.gpu.u32 [%0], %1;" :: "l"(p), "r"(v) : "memory");
}
__device__ __forceinline__ void cnt_add(unsigned* p) {
    asm volatile("red.release.gpu.global.add.u32 [%0], 1;" :: "l"(p) : "memory");
}
__device__ __forceinline__ float ldcv_half(const __half* p) {
    unsigned short v;
    asm volatile("ld.global.cv.u16 %0, [%1];" : "=h"(v) : "l"(p));
    return __half2float(__ushort_as_half(v));
}
__device__ __forceinline__ float sigf(float x) {
    float e = __expf(-x);
    return __fdividef(1.f, 1.f + e);
}
__device__ __forceinline__ float tanhfast(float z) {
    float e = __expf(-2.f * z);
    return __fdividef(2.f, 1.f + e) - 1.f;
}
__device__ __forceinline__ void cnt_poll(const unsigned* p, unsigned tgt) {
    while (flag_acq(p) < tgt) { }
}

// ---------------- single persistent clustered kernel ----------------
__global__ void __launch_bounds__(TB, 1) __cluster_dims__(CL, 1, 1) k_lstm(
    const float* __restrict__ x,
    const int*   __restrict__ lengths,
    const float* __restrict__ Wih0, const float* __restrict__ Whh0, const float* __restrict__ bb0,
    const float* __restrict__ Wih1, const float* __restrict__ Whh1, const float* __restrict__ bb1,
    const float* __restrict__ Wih2, const float* __restrict__ Whh2, const float* __restrict__ bb2,
    const float* __restrict__ fcw,  const float* __restrict__ fcb,
    float* __restrict__ out)
{
    extern __shared__ unsigned char smem[];
    unsigned long long* sW = (unsigned long long*)(smem + OFF_W);
    __half* sXh = (__half*)(smem + OFF_X);
    float*  sP  = (float*)(smem + OFF_P);
    float*  sC  = (float*)(smem + OFF_C);
    float*  sB  = (float*)(smem + OFF_B);
    int*    sLen= (int*)  (smem + OFF_L);
    unsigned mb0 = (unsigned)__cvta_generic_to_shared(smem + OFF_M);

    const int tid = threadIdx.x;
    const int cta = blockIdx.x;
    const int l   = cta / NCOL;
    const int cb  = cta - l * NCOL;
    const int j0  = cb * JT;
    unsigned cr;
    asm("mov.u32 %0, %%cluster_ctarank;" : "=r"(cr));

    const unsigned base = g_flag[cta * 32];   // replay-safe Phase-A base

    const float *Wih, *Whh, *bias;
    int DX;                                   // x-input rows
    if (l == 0)      { Wih = Wih0; Whh = Whh0; bias = bb0; DX = DD; }
    else if (l == 1) { Wih = Wih1; Whh = Whh1; bias = bb1; DX = H_PAD; }
    else             { Wih = Wih2; Whh = Whh2; bias = bb2; DX = H_PAD; }
    const int KTOT = H_PAD + DX;                   // 208 or 336 (h rows FIRST)
    const int Q    = KTOT / NCHUNK;                // 52 or 84
    const int S    = (Q + CL - 1) / CL;

    // ---------- Phase A ----------
    // h-block weights (rows k in [0, H_PAD)): Whh
    for (int idx = tid; idx < H_PAD * 16; idx += TB) {
        int k = idx >> 4, r = idx & 15;
        int g = r >> 2, jj = r & 3;
        int j = j0 + jj;
        float w = (j < HH && k < HH) ? Whh[(g * HH + j) * HH + k] : 0.f;
        sW[k * 16 + r] = splat2(w);
    }
    // x-block weights (rows k in [H_PAD, KTOT)): Wih
    for (int idx = tid; idx < DX * 16; idx += TB) {
        int k = idx >> 4, r = idx & 15;
        int g = r >> 2, jj = r & 3;
        int j = j0 + jj;
        float w = 0.f;
        if (j < HH) {
            if (l == 0)            w = Wih[(g * HH + j) * DD + k];
            else if (k < HH)       w = Wih[(g * HH + j) * HH + k];
        }
        sW[(H_PAD + k) * 16 + r] = splat2(w);
    }
    if (tid < 16) {
        int g = tid >> 2, jj = tid & 3;
        int j = j0 + jj;
        sB[tid] = (j < HH) ? bias[g * HH + j] : 0.f;
    }
    if (tid < BB) sLen[tid] = lengths[tid];
    if (tid < JT * BB) sC[tid] = 0.f;
    if (tid == 0) {
        #pragma unroll
        for (int c = 0; c < NCHUNK; ++c) mbar_init(mb0 + c * 8, 1);
    }
    if (cta == 0 && tid < NLAYER * NSLOT) g_cnt[tid * 32] = 0u;
    {
        unsigned* gh32 = (unsigned*)g_h;
        const int NH = (NLAYER * RS * H_PAD * BB) / 2;
        for (int i = cta * TB + tid; i < NH; i += NCTA * TB) gh32[i] = 0u;
    }
    {
        float* scratch = (float*)(smem + OFF_X);
        for (int t = cta; t < TT; t += NCTA) {
            __syncthreads();
            for (int idx = tid; idx < BB * DD; idx += TB) {
                int b = idx / DD, d = idx - b * DD;
                scratch[idx] = x[(b * TT + t) * DD + d];
            }
            __syncthreads();
            for (int idx = tid; idx < BB * DD; idx += TB) {
                int d = idx >> 6, b = idx & 63;
                g_xTh[t * DD * BB + idx] = __float2half_rn(scratch[b * DD + d]);
            }
        }
    }
    __syncthreads();
    asm volatile("barrier.cluster.arrive.aligned;" ::: "memory");
    asm volatile("barrier.cluster.wait.aligned;" ::: "memory");
    if (tid == 0) {
        #pragma unroll
        for (int c = 0; c < NCHUNK; ++c)
            mbar_expect_tx(mb0 + c * 8, (unsigned)(Q * BB * 2));
        asm volatile("fence.proxy.async;" ::: "memory");
        flag_rel(g_flag + cta * 32, base + 1);
    }
    if (tid < NCTA) {
        while (flag_acq(g_flag + tid * 32) < base + 1) { }
    }
    __syncthreads();

    const int lane = tid & 31;
    const int warp = tid >> 5;
    const int kg   = warp >> 1;
    const int r0   = (warp & 1) * 8 + (lane >> 4) * 4;
    const int b0i  = (lane & 15) * 4;
    const int kb   = kg * Q;
    const unsigned short mcmask = (1u << CL) - 1u;

    // ---------- main loop ----------
    for (int u = 0; u < TT; ++u) {
        const unsigned par = (unsigned)(u & 1);

        const __half* hin = g_h + (l * RS + ((u + RS - 1) & (RS - 1))) * H_PAD * BB;
        const __half* xin = (l == 0) ? (g_xTh + u * DD * BB)
                                     : (g_h + ((l - 1) * RS + (u & (RS - 1))) * H_PAD * BB);

        // slice issue helper (this CTA's multicast slice of chunk c)
        auto issue_chunk = [&](int c) {
            int rb = c * Q;
            int re = rb + Q;
            int sb = rb + (int)cr * S;
            int se = min(sb + S, re);
            if (se > sb) {
                int h1 = min(se, H_PAD);
                if (h1 > sb)
                    mc_g2s(sXh + sb * BB, hin + sb * BB,
                           (h1 - sb) * BB * 2, mb0 + c * 8, mcmask);
                int x0 = max(sb, H_PAD);
                if (se > x0)
                    mc_g2s(sXh + x0 * BB, xin + (x0 - H_PAD) * BB,
                           (se - x0) * BB * 2, mb0 + c * 8, mcmask);
            }
        };

        if (tid == 0) {
            // own-layer recurrence gate (h side) + ring-overwrite gate
            if (u >= 1) {
                const int v = u - 1;
                cnt_poll(g_cnt + (l * NSLOT + (v & (NSLOT - 1))) * 32,
                         (unsigned)NCOL * ((unsigned)(v >> 3) + 1u));
            }
            if (l < NLAYER - 1 && u >= RS) {
                const int v = u - RS;
                cnt_poll(g_cnt + ((l + 1) * NSLOT + (v & (NSLOT - 1))) * 32,
                         (unsigned)NCOL * ((unsigned)(v >> 3) + 1u));
            }
            issue_chunk(0);
            issue_chunk(1);
            if (l == 0) { issue_chunk(2); issue_chunk(3); }   // x static: own-gated only
        }
        if (tid == 128 && l > 0) {
            // x side: gated on own@u-1 (ensures arming done) + producer@u
            if (u >= 1) {
                const int v = u - 1;
                cnt_poll(g_cnt + (l * NSLOT + (v & (NSLOT - 1))) * 32,
                         (unsigned)NCOL * ((unsigned)(v >> 3) + 1u));
            }
            cnt_poll(g_cnt + ((l - 1) * NSLOT + (u & (NSLOT - 1))) * 32,
                     (unsigned)NCOL * ((unsigned)(u >> 3) + 1u));
            issue_chunk(2);
            issue_chunk(3);
        }

        // ---- wait this warp's chunk, then GEMM ----
        mbar_wait(mb0 + kg * 8, par);

        const int ke = kb + Q;
        unsigned long long a0, a1, a2, a3, a4, a5, a6, a7;
        if (kg == 0) {
            a0 = a1 = splat2(sB[r0 + 0]);
            a2 = a3 = splat2(sB[r0 + 1]);
            a4 = a5 = splat2(sB[r0 + 2]);
            a6 = a7 = splat2(sB[r0 + 3]);
        } else {
            a0 = a1 = a2 = a3 = a4 = a5 = a6 = a7 = 0ull;
        }

        #pragma unroll 4
        for (int k = kb; k < ke; ++k) {
            uint2 xh = *(const uint2*)(sXh + k * BB + b0i);
            __half2 hA = *reinterpret_cast<__half2*>(&xh.x);
            __half2 hB = *reinterpret_cast<__half2*>(&xh.y);
            float2 fA = __half22float2(hA);
            float2 fB = __half22float2(hB);
            unsigned long long xA = pack2(fA.x, fA.y);
            unsigned long long xB = pack2(fB.x, fB.y);
            ulonglong2 wA = *(const ulonglong2*)(sW + k * 16 + r0);
            ulonglong2 wB = *(const ulonglong2*)(sW + k * 16 + r0 + 2);
            a0 = fma2(xA, wA.x, a0);  a1 = fma2(xB, wA.x, a1);
            a2 = fma2(xA, wA.y, a2);  a3 = fma2(xB, wA.y, a3);
            a4 = fma2(xA, wB.x, a4);  a5 = fma2(xB, wB.x, a5);
            a6 = fma2(xA, wB.y, a6);  a7 = fma2(xB, wB.y, a7);
        }

        float* pp = sP + kg * (16 * BB);
        *(ulonglong2*)(pp + (r0 + 0) * BB + b0i) = make_ulonglong2(a0, a1);
        *(ulonglong2*)(pp + (r0 + 1) * BB + b0i) = make_ulonglong2(a2, a3);
        *(ulonglong2*)(pp + (r0 + 2) * BB + b0i) = make_ulonglong2(a4, a5);
        *(ulonglong2*)(pp + (r0 + 3) * BB + b0i) = make_ulonglong2(a6, a7);
        __syncthreads();

        // ---- elementwise + state update ----
        {
            __half* hout = g_h + (l * RS + (u & (RS - 1))) * H_PAD * BB;
            int b = tid & 63, jj = tid >> 6;
            float iv = 0.f, fv = 0.f, gv = 0.f, ov = 0.f;
            #pragma unroll
            for (int c = 0; c < NCHUNK; ++c) {
                const float* p = sP + c * (16 * BB);
                iv += p[(0  + jj) * BB + b];
                fv += p[(4  + jj) * BB + b];
                gv += p[(8  + jj) * BB + b];
                ov += p[(12 + jj) * BB + b];
            }
            float co = sC[jj * BB + b];
            float cn = sigf(fv) * co + sigf(iv) * tanhfast(gv);
            float hn = sigf(ov) * tanhfast(cn);
            bool  m  = (u < sLen[b]);
            int   j  = j0 + jj;
            __half hpv = sXh[j * BB + b];        // h rows now at offset 0
            sC[jj * BB + b]  = m ? cn : co;
            hout[j * BB + b] = m ? __float2half_rn(hn) : hpv;
        }
        __syncthreads();

        if (tid == 0) {
            if (u + 1 < TT) {
                #pragma unroll
                for (int c = 0; c < NCHUNK; ++c)
                    mbar_expect_tx(mb0 + c * 8, (unsigned)(Q * BB * 2));
            }
            asm volatile("fence.proxy.async;" ::: "memory");
            cnt_add(g_cnt + (l * NSLOT + (u & (NSLOT - 1))) * 32);
        }
    }

    // ---------- final FC on CTA 0 ----------
    if (cta == 0) {
        if (tid == 0) {
            const int v = TT - 1;
            cnt_poll(g_cnt + (2 * NSLOT + (v & (NSLOT - 1))) * 32,
                     (unsigned)NCOL * ((unsigned)(v >> 3) + 1u));
        }
        __syncthreads();
        const __half* h2 = g_h + (2 * RS + ((TT - 1) & (RS - 1))) * H_PAD * BB;
        for (int it = tid; it < BB * NOUT; it += TB) {
            int b = it / NOUT, o = it - b * NOUT;
            float acc = fcb[o];
            #pragma unroll 4
            for (int j = 0; j < HH; ++j)
                acc += ldcv_half(h2 + j * BB + b) * fcw[o * HH + j];
            out[b * NOUT + o] = acc;
        }
        __syncthreads();
    }

    if (tid == 0) flag_rel(g_flag + cta * 32, base + (unsigned)TT + 8);

    asm volatile("barrier.cluster.arrive.aligned;" ::: "memory");
    asm volatile("barrier.cluster.wait.aligned;" ::: "memory");
}

// ---------------- launch ----------------
extern "C" void kernel_launch(void* const* d_in, const int* in_sizes, int n_in,
                              void* d_out, int out_size) {
    const float* x       = (const float*)d_in[0];
    const int*   lengths = (const int*)  d_in[1];
    const float* Wih0    = (const float*)d_in[2];
    const float* Whh0    = (const float*)d_in[3];
    const float* b0      = (const float*)d_in[4];
    const float* Wih1    = (const float*)d_in[5];
    const float* Whh1    = (const float*)d_in[6];
    const float* b1      = (const float*)d_in[7];
    const float* Wih2    = (const float*)d_in[8];
    const float* Whh2    = (const float*)d_in[9];
    const float* b2      = (const float*)d_in[10];
    const float* fcw     = (const float*)d_in[11];
    const float* fcb     = (const float*)d_in[12];
    float* out = (float*)d_out;

    static bool attr_set = false;
    if (!attr_set) {
        cudaFuncSetAttribute(k_lstm, cudaFuncAttributeMaxDynamicSharedMemorySize, SMEM_BYTES);
        attr_set = true;
    }

    k_lstm<<<NCTA, TB, SMEM_BYTES>>>(x, lengths,
                                     Wih0, Whh0, b0,
                                     Wih1, Whh1, b1,
                                     Wih2, Whh2, b2,
                                     fcw, fcb, out);
}

// round 11
// speedup vs baseline: 2.1920x; 2.1920x over previous
#include <cuda_runtime.h>
#include <cuda_fp16.h>
#include <math.h>

// Problem constants
#define BB     64
#define TT     2048
#define DD     40
#define HH     164
#define H_PAD  168             // padded hidden (42 CTAs x 4 cols); pad rows stay exactly 0
#define NOUT   7
#define JT     4
#define NCOL   42              // CTAs per layer
#define NLAYER 3
#define NCTA   (NCOL * NLAYER) // 126
#define CL     3               // cluster size (same-layer triples)
#define TB     256             // 8 warps
#define KMAX   (H_PAD + H_PAD) // 336
#define NCHUNK 4
#define RS     4               // h ring depth -> consumer lag 3
#define NSLOT  8               // counter slots per layer

// ---- dynamic smem layout (bytes) ----
#define OFF_W   0
#define SZ_W    (KMAX * 16 * 8)            // splatted fp32 weights: 43008
#define OFF_X   (OFF_W + SZ_W)
#define SZ_X    (KMAX * BB * 2)            // staged [x;h] fp16: 43008
#define OFF_P   (OFF_X + SZ_X)
#define SZ_P    (NCHUNK * 16 * BB * 4)     // k-split partials: 16384
#define OFF_C   (OFF_P + SZ_P)
#define SZ_C    (JT * BB * 4)
#define OFF_B   (OFF_C + SZ_C)
#define SZ_B    (16 * 4)
#define OFF_L   (OFF_B + SZ_B)
#define SZ_L    (BB * 4)
#define OFF_M   (OFF_L + SZ_L)
#define SZ_M    (NCHUNK * 8)
#define SMEM_BYTES (OFF_M + SZ_M)          // ~104 KB

// ---------------- device scratch ----------------
__device__ __align__(256) __half g_xTh[TT * DD * BB];            // x fp16: [t][d][b]
__device__ __align__(256) __half g_h[NLAYER * RS * H_PAD * BB];  // h ring fp16
__device__ unsigned g_flag[NCTA * 32];                           // Phase-A barrier flags only
__device__ __align__(128) unsigned g_cnt[NLAYER * NSLOT * 32];   // arrival counters, 128B apart

// ---------------- helpers ----------------
__device__ __forceinline__ unsigned long long fma2(unsigned long long a,
                                                   unsigned long long b,
                                                   unsigned long long c) {
    unsigned long long d;
    asm("fma.rn.f32x2 %0, %1, %2, %3;" : "=l"(d) : "l"(a), "l"(b), "l"(c));
    return d;
}
__device__ __forceinline__ unsigned long long splat2(float w) {
    unsigned long long v = (unsigned long long)__float_as_uint(w);
    return v | (v << 32);
}
__device__ __forceinline__ unsigned long long pack2(float lo, float hi) {
    unsigned long long r;
    asm("mov.b64 %0, {%1, %2};" : "=l"(r) : "f"(lo), "f"(hi));
    return r;
}
__device__ __forceinline__ void mc_g2s(void* dst_smem, const void* src, int bytes,
                                       unsigned mbar, unsigned short mask) {
    unsigned d = (unsigned)__cvta_generic_to_shared(dst_smem);
    asm volatile(
        "cp.async.bulk.shared::cluster.global.mbarrier::complete_tx::bytes.multicast::cluster"
        " [%0], [%1], %2, [%3], %4;"
        :: "r"(d), "l"(src), "r"(bytes), "r"(mbar), "h"(mask) : "memory");
}
__device__ __forceinline__ void mbar_init(unsigned addr, unsigned cnt) {
    asm volatile("mbarrier.init.shared.b64 [%0], %1;" :: "r"(addr), "r"(cnt) : "memory");
}
__device__ __forceinline__ void mbar_expect_tx(unsigned addr, unsigned bytes) {
    asm volatile("mbarrier.arrive.expect_tx.shared.b64 _, [%0], %1;" :: "r"(addr), "r"(bytes) : "memory");
}
__device__ __forceinline__ void mbar_wait(unsigned addr, unsigned parity) {
    asm volatile(
        "{\n\t"
        ".reg .pred P1;\n\t"
        "WAIT_%=:\n\t"
        "mbarrier.try_wait.parity.acquire.cta.shared::cta.b64 P1, [%0], %1, 0x989680;\n\t"
        "@P1 bra DONE_%=;\n\t"
        "bra WAIT_%=;\n\t"
        "DONE_%=:\n\t"
        "}"
        :: "r"(addr), "r"(parity) : "memory");
}
__device__ __forceinline__ unsigned flag_acq(const unsigned* p) {
    unsigned r;
    asm volatile("ld.global.acquire.gpu.u32 %0, [%1];" : "=r"(r) : "l"(p));
    return r;
}
__device__ __forceinline__ void flag_rel(unsigned* p, unsigned v) {
    asm volatile("st.global.release.gpu.u32 [%0], %1;" :: "l"(p), "r"(v) : "memory");
}
__device__ __forceinline__ void cnt_add(unsigned* p) {
    asm volatile("red.release.gpu.global.add.u32 [%0], 1;" :: "l"(p) : "memory");
}
__device__ __forceinline__ float ldcv_half(const __half* p) {
    unsigned short v;
    asm volatile("ld.global.cv.u16 %0, [%1];" : "=h"(v) : "l"(p));
    return __half2float(__ushort_as_half(v));
}
__device__ __forceinline__ float sigf(float x) {
    float e = __expf(-x);
    return __fdividef(1.f, 1.f + e);
}
__device__ __forceinline__ float tanhfast(float z) {
    float e = __expf(-2.f * z);
    return __fdividef(2.f, 1.f + e) - 1.f;
}

// ---------------- single persistent clustered kernel ----------------
__global__ void __launch_bounds__(TB, 1) __cluster_dims__(CL, 1, 1) k_lstm(
    const float* __restrict__ x,
    const int*   __restrict__ lengths,
    const float* __restrict__ Wih0, const float* __restrict__ Whh0, const float* __restrict__ bb0,
    const float* __restrict__ Wih1, const float* __restrict__ Whh1, const float* __restrict__ bb1,
    const float* __restrict__ Wih2, const float* __restrict__ Whh2, const float* __restrict__ bb2,
    const float* __restrict__ fcw,  const float* __restrict__ fcb,
    float* __restrict__ out)
{
    extern __shared__ unsigned char smem[];
    unsigned long long* sW = (unsigned long long*)(smem + OFF_W);
    __half* sXh = (__half*)(smem + OFF_X);
    float*  sP  = (float*)(smem + OFF_P);
    float*  sC  = (float*)(smem + OFF_C);
    float*  sB  = (float*)(smem + OFF_B);
    int*    sLen= (int*)  (smem + OFF_L);
    unsigned mb0 = (unsigned)__cvta_generic_to_shared(smem + OFF_M);

    const int tid = threadIdx.x;
    const int cta = blockIdx.x;
    const int l   = cta / NCOL;
    const int cb  = cta - l * NCOL;
    const int j0  = cb * JT;
    unsigned cr;
    asm("mov.u32 %0, %%cluster_ctarank;" : "=r"(cr));

    const unsigned base = g_flag[cta * 32];   // replay-safe Phase-A base

    const float *Wih, *Whh, *bias;
    int Din;
    if (l == 0)      { Wih = Wih0; Whh = Whh0; bias = bb0; Din = DD; }
    else if (l == 1) { Wih = Wih1; Whh = Whh1; bias = bb1; Din = H_PAD; }
    else             { Wih = Wih2; Whh = Whh2; bias = bb2; Din = H_PAD; }
    const int KTOT = Din + H_PAD;                  // 208 or 336
    const int Q    = KTOT / NCHUNK;                // 52 or 84
    const int S    = (Q + CL - 1) / CL;

    // ---------- Phase A ----------
    for (int idx = tid; idx < Din * 16; idx += TB) {
        int k = idx >> 4, r = idx & 15;
        int g = r >> 2, jj = r & 3;
        int j = j0 + jj;
        float w = 0.f;
        if (j < HH) {
            if (l == 0)            w = Wih[(g * HH + j) * DD + k];
            else if (k < HH)       w = Wih[(g * HH + j) * HH + k];
        }
        sW[k * 16 + r] = splat2(w);
    }
    for (int idx = tid; idx < H_PAD * 16; idx += TB) {
        int k = idx >> 4, r = idx & 15;
        int g = r >> 2, jj = r & 3;
        int j = j0 + jj;
        float w = (j < HH && k < HH) ? Whh[(g * HH + j) * HH + k] : 0.f;
        sW[(Din + k) * 16 + r] = splat2(w);
    }
    if (tid < 16) {
        int g = tid >> 2, jj = tid & 3;
        int j = j0 + jj;
        sB[tid] = (j < HH) ? bias[g * HH + j] : 0.f;
    }
    if (tid < BB) sLen[tid] = lengths[tid];
    if (tid < JT * BB) sC[tid] = 0.f;
    if (tid == 0) {
        #pragma unroll
        for (int c = 0; c < NCHUNK; ++c) mbar_init(mb0 + c * 8, 1);
    }
    // cta 0 zeroes the arrival counters (visible via its Phase-A release flag)
    if (cta == 0 && tid < NLAYER * NSLOT) g_cnt[tid * 32] = 0u;
    // zero h ring
    {
        unsigned* gh32 = (unsigned*)g_h;
        const int NH = (NLAYER * RS * H_PAD * BB) / 2;
        for (int i = cta * TB + tid; i < NH; i += NCTA * TB) gh32[i] = 0u;
    }
    // transpose+convert x[B][T][D] -> g_xTh[t][d][b]
    {
        float* scratch = (float*)(smem + OFF_X);
        for (int t = cta; t < TT; t += NCTA) {
            __syncthreads();
            for (int idx = tid; idx < BB * DD; idx += TB) {
                int b = idx / DD, d = idx - b * DD;
                scratch[idx] = x[(b * TT + t) * DD + d];
            }
            __syncthreads();
            for (int idx = tid; idx < BB * DD; idx += TB) {
                int d = idx >> 6, b = idx & 63;
                g_xTh[t * DD * BB + idx] = __float2half_rn(scratch[b * DD + d]);
            }
        }
    }
    __syncthreads();
    // cluster barrier: mbarrier inits visible before peer multicast
    asm volatile("barrier.cluster.arrive.aligned;" ::: "memory");
    asm volatile("barrier.cluster.wait.aligned;" ::: "memory");
    // arm step-0 mbarriers, then Phase-A global barrier (once per launch)
    if (tid == 0) {
        #pragma unroll
        for (int c = 0; c < NCHUNK; ++c)
            mbar_expect_tx(mb0 + c * 8, (unsigned)(Q * BB * 2));
        asm volatile("fence.proxy.async;" ::: "memory");
        flag_rel(g_flag + cta * 32, base + 1);
    }
    if (tid < NCTA) {
        while (flag_acq(g_flag + tid * 32) < base + 1) { }
    }
    __syncthreads();

    const int lane = tid & 31;
    const int warp = tid >> 5;
    const int kg   = warp >> 1;
    const int r0   = (warp & 1) * 8 + (lane >> 4) * 4;
    const int b0i  = (lane & 15) * 4;
    const int kb   = kg * Q;
    const unsigned short mcmask = (1u << CL) - 1u;

    // ---------- main loop ----------
    for (int u = 0; u < TT; ++u) {
        const unsigned par = (unsigned)(u & 1);

        const __half* xin = (l == 0) ? (g_xTh + u * DD * BB)
                                     : (g_h + ((l - 1) * RS + (u & (RS - 1))) * H_PAD * BB);
        const __half* hin = g_h + (l * RS + ((u + RS - 1) & (RS - 1))) * H_PAD * BB;

        if (warp == 0) {
            // 3-counter dependency wait: lane0=producer@u, lane1=own@u-1, lane2=consumer@u-4
            if (lane == 0 && l > 0) {
                const unsigned* p = g_cnt + ((l - 1) * NSLOT + (u & (NSLOT - 1))) * 32;
                const unsigned tgt = (unsigned)NCOL * ((unsigned)(u >> 3) + 1u);
                while (flag_acq(p) < tgt) { }
            }
            if (lane == 1 && u >= 1) {
                const int v = u - 1;
                const unsigned* p = g_cnt + (l * NSLOT + (v & (NSLOT - 1))) * 32;
                const unsigned tgt = (unsigned)NCOL * ((unsigned)(v >> 3) + 1u);
                while (flag_acq(p) < tgt) { }
            }
            if (lane == 2 && l < NLAYER - 1 && u >= RS) {
                const int v = u - RS;
                const unsigned* p = g_cnt + ((l + 1) * NSLOT + (v & (NSLOT - 1))) * 32;
                const unsigned tgt = (unsigned)NCOL * ((unsigned)(v >> 3) + 1u);
                while (flag_acq(p) < tgt) { }
            }
            __syncwarp();
            if (lane == 0) {
                // issue THIS CTA's multicast slices of each chunk
                #pragma unroll
                for (int c = 0; c < NCHUNK; ++c) {
                    int rb = c * Q;
                    int re = rb + Q;
                    int sb = rb + (int)cr * S;
                    int se = min(sb + S, re);
                    if (se > sb) {
                        int x1 = min(se, Din);
                        if (x1 > sb)
                            mc_g2s(sXh + sb * BB, xin + sb * BB,
                                   (x1 - sb) * BB * 2, mb0 + c * 8, mcmask);
                        int h0 = max(sb, Din);
                        if (se > h0)
                            mc_g2s(sXh + h0 * BB, hin + (h0 - Din) * BB,
                                   (se - h0) * BB * 2, mb0 + c * 8, mcmask);
                    }
                }
            }
            __syncwarp();
        }

        // ---- wait this warp's chunk, then GEMM ----
        mbar_wait(mb0 + kg * 8, par);

        const int ke = kb + Q;
        unsigned long long a0, a1, a2, a3, a4, a5, a6, a7;
        if (kg == 0) {
            a0 = a1 = splat2(sB[r0 + 0]);
            a2 = a3 = splat2(sB[r0 + 1]);
            a4 = a5 = splat2(sB[r0 + 2]);
            a6 = a7 = splat2(sB[r0 + 3]);
        } else {
            a0 = a1 = a2 = a3 = a4 = a5 = a6 = a7 = 0ull;
        }

        #pragma unroll 4
        for (int k = kb; k < ke; ++k) {
            uint2 xh = *(const uint2*)(sXh + k * BB + b0i);
            __half2 hA = *reinterpret_cast<__half2*>(&xh.x);
            __half2 hB = *reinterpret_cast<__half2*>(&xh.y);
            float2 fA = __half22float2(hA);
            float2 fB = __half22float2(hB);
            unsigned long long xA = pack2(fA.x, fA.y);
            unsigned long long xB = pack2(fB.x, fB.y);
            ulonglong2 wA = *(const ulonglong2*)(sW + k * 16 + r0);
            ulonglong2 wB = *(const ulonglong2*)(sW + k * 16 + r0 + 2);
            a0 = fma2(xA, wA.x, a0);  a1 = fma2(xB, wA.x, a1);
            a2 = fma2(xA, wA.y, a2);  a3 = fma2(xB, wA.y, a3);
            a4 = fma2(xA, wB.x, a4);  a5 = fma2(xB, wB.x, a5);
            a6 = fma2(xA, wB.y, a6);  a7 = fma2(xB, wB.y, a7);
        }

        float* pp = sP + kg * (16 * BB);
        *(ulonglong2*)(pp + (r0 + 0) * BB + b0i) = make_ulonglong2(a0, a1);
        *(ulonglong2*)(pp + (r0 + 1) * BB + b0i) = make_ulonglong2(a2, a3);
        *(ulonglong2*)(pp + (r0 + 2) * BB + b0i) = make_ulonglong2(a4, a5);
        *(ulonglong2*)(pp + (r0 + 3) * BB + b0i) = make_ulonglong2(a6, a7);
        __syncthreads();   // all chunk phases complete past this point

        // EARLY ARMING: re-arm next step's mbarriers now (all current phases done).
        // Peers <=1 step ahead can deliver u+1 slices during our epilogue.
        if (tid == 0 && u + 1 < TT) {
            #pragma unroll
            for (int c = 0; c < NCHUNK; ++c)
                mbar_expect_tx(mb0 + c * 8, (unsigned)(Q * BB * 2));
        }

        // ---- elementwise + state update ----
        {
            __half* hout = g_h + (l * RS + (u & (RS - 1))) * H_PAD * BB;
            int b = tid & 63, jj = tid >> 6;
            float iv = 0.f, fv = 0.f, gv = 0.f, ov = 0.f;
            #pragma unroll
            for (int c = 0; c < NCHUNK; ++c) {
                const float* p = sP + c * (16 * BB);
                iv += p[(0  + jj) * BB + b];
                fv += p[(4  + jj) * BB + b];
                gv += p[(8  + jj) * BB + b];
                ov += p[(12 + jj) * BB + b];
            }
            float co = sC[jj * BB + b];
            float cn = sigf(fv) * co + sigf(iv) * tanhfast(gv);
            float hn = sigf(ov) * tanhfast(cn);
            bool  m  = (u < sLen[b]);
            int   j  = j0 + jj;
            __half hpv = sXh[(Din + j) * BB + b];
            sC[jj * BB + b]  = m ? cn : co;
            hout[j * BB + b] = m ? __float2half_rn(hn) : hpv;
        }
        __syncthreads();

        if (tid == 0) {
            asm volatile("fence.proxy.async;" ::: "memory");
            cnt_add(g_cnt + (l * NSLOT + (u & (NSLOT - 1))) * 32);
        }
    }

    // ---------- final FC on CTA 0 ----------
    if (cta == 0) {
        if (tid == 0) {
            const int v = TT - 1;
            const unsigned* p = g_cnt + (2 * NSLOT + (v & (NSLOT - 1))) * 32;
            const unsigned tgt = (unsigned)NCOL * ((unsigned)(v >> 3) + 1u);
            while (flag_acq(p) < tgt) { }
        }
        __syncthreads();
        const __half* h2 = g_h + (2 * RS + ((TT - 1) & (RS - 1))) * H_PAD * BB;
        for (int it = tid; it < BB * NOUT; it += TB) {
            int b = it / NOUT, o = it - b * NOUT;
            float acc = fcb[o];
            #pragma unroll 4
            for (int j = 0; j < HH; ++j)
                acc += ldcv_half(h2 + j * BB + b) * fcw[o * HH + j];
            out[b * NOUT + o] = acc;
        }
        __syncthreads();
    }

    if (tid == 0) flag_rel(g_flag + cta * 32, base + (unsigned)TT + 8);

    // cluster members exit together
    asm volatile("barrier.cluster.arrive.aligned;" ::: "memory");
    asm volatile("barrier.cluster.wait.aligned;" ::: "memory");
}

// ---------------- launch ----------------
extern "C" void kernel_launch(void* const* d_in, const int* in_sizes, int n_in,
                              void* d_out, int out_size) {
    const float* x       = (const float*)d_in[0];
    const int*   lengths = (const int*)  d_in[1];
    const float* Wih0    = (const float*)d_in[2];
    const float* Whh0    = (const float*)d_in[3];
    const float* b0      = (const float*)d_in[4];
    const float* Wih1    = (const float*)d_in[5];
    const float* Whh1    = (const float*)d_in[6];
    const float* b1      = (const float*)d_in[7];
    const float* Wih2    = (const float*)d_in[8];
    const float* Whh2    = (const float*)d_in[9];
    const float* b2      = (const float*)d_in[10];
    const float* fcw     = (const float*)d_in[11];
    const float* fcb     = (const float*)d_in[12];
    float* out = (float*)d_out;

    static bool attr_set = false;
    if (!attr_set) {
        cudaFuncSetAttribute(k_lstm, cudaFuncAttributeMaxDynamicSharedMemorySize, SMEM_BYTES);
        attr_set = true;
    }

    k_lstm<<<NCTA, TB, SMEM_BYTES>>>(x, lengths,
                                     Wih0, Whh0, b0,
                                     Wih1, Whh1, b1,
                                     Wih2, Whh2, b2,
                                     fcw, fcb, out);
}